// round 3
// baseline (speedup 1.0000x reference)
#include <cuda_runtime.h>
#include <cstdint>

#define BB 8
#define SS 1024
#define FEAT 1024
#define HIDD 1024
#define HH 8
#define DHH 128
#define MTOT (BB*SS)

// tf32-rounded Q/K/V (bit patterns stored as uint32)
__device__ uint32_t g_Q[MTOT*HIDD];
__device__ uint32_t g_K[MTOT*HIDD];
__device__ uint32_t g_V[MTOT*HIDD];

__device__ __forceinline__ uint32_t f2t(float x) {
    uint32_t u;
    asm("cvt.rna.tf32.f32 %0, %1;" : "=r"(u) : "f"(x));
    return u;
}
__device__ __forceinline__ uint32_t smaddr(const void* p) {
    return (uint32_t)__cvta_generic_to_shared(p);
}

#define CP16(dst,src) asm volatile("cp.async.cg.shared.global [%0], [%1], 16;" :: "r"(dst), "l"(src))
#define CPCOMMIT()    asm volatile("cp.async.commit_group;")
#define CPWAIT(n)     asm volatile("cp.async.wait_group %0;" :: "n"(n))

__device__ __forceinline__ void mma8(float* d, const uint32_t* a, const uint32_t* b) {
    asm volatile(
        "mma.sync.aligned.m16n8k8.row.col.f32.tf32.tf32.f32 "
        "{%0,%1,%2,%3}, {%4,%5,%6,%7}, {%8,%9}, {%0,%1,%2,%3};"
        : "+f"(d[0]), "+f"(d[1]), "+f"(d[2]), "+f"(d[3])
        : "r"(a[0]), "r"(a[1]), "r"(a[2]), "r"(a[3]), "r"(b[0]), "r"(b[1]));
}

// ---------------------------------------------------------------------------
// Pass 1: QKV projection GEMM, tf32 mma.sync, raw-fp32 inputs converted at
// fragment-read time (cvt.rna). Block 128 threads (4 warps, 64x64 each),
// block tile 128x128, K-step 32, cp.async double-buffered.
// ---------------------------------------------------------------------------
#define AS_STR 36
#define WS_STR 132
#define AS_SZ (128*AS_STR)
#define WS_SZ (32*WS_STR)
#define STG   (AS_SZ + WS_SZ)
#define GSM_BYTES (2*STG*4)

__global__ __launch_bounds__(128)
void qkv_mma_kernel(const float* __restrict__ A,
                    const float* __restrict__ Wq, const float* __restrict__ bq,
                    const float* __restrict__ Wk, const float* __restrict__ bk,
                    const float* __restrict__ Wv, const float* __restrict__ bv)
{
    extern __shared__ float smg[];
    const int tid = threadIdx.x;
    const int w = tid >> 5, lane = tid & 31;
    const int g = lane >> 2, t = lane & 3;
    const int mw = (w >> 1) * 64, nw = (w & 1) * 64;
    const int row0 = blockIdx.y * 128, col0 = blockIdx.x * 128;

    const float* Wg   = (blockIdx.z == 0) ? Wq  : (blockIdx.z == 1 ? Wk  : Wv);
    const float* bias = (blockIdx.z == 0) ? bq  : (blockIdx.z == 1 ? bk  : bv);
    uint32_t* Og      = (blockIdx.z == 0) ? g_Q : (blockIdx.z == 1 ? g_K : g_V);

    float acc[4][8][4];
#pragma unroll
    for (int i = 0; i < 4; i++)
#pragma unroll
        for (int j = 0; j < 8; j++)
#pragma unroll
            for (int e = 0; e < 4; e++) acc[i][j][e] = 0.0f;

    auto issue = [&](int it) {
        int st = it & 1;
        uint32_t base = smaddr(smg + st*STG);
        int k0 = it * 32;
#pragma unroll
        for (int c = 0; c < 8; c++) {
            int slot = tid + c*128;
            int r = slot >> 3, kc = (slot & 7) * 4;
            CP16(base + (r*AS_STR + kc)*4, A + (long)(row0 + r)*FEAT + k0 + kc);
        }
        uint32_t baseW = base + AS_SZ*4;
#pragma unroll
        for (int c = 0; c < 8; c++) {
            int slot = tid + c*128;
            int r = slot >> 5, nc = (slot & 31) * 4;
            CP16(baseW + (r*WS_STR + nc)*4, Wg + (long)(k0 + r)*HIDD + col0 + nc);
        }
    };

    issue(0); CPCOMMIT();
    for (int it = 0; it < 32; ++it) {
        if (it + 1 < 32) issue(it + 1);
        CPCOMMIT();
        CPWAIT(1);
        __syncthreads();
        const float* As = smg + (it & 1)*STG;
        const float* Ws = As + AS_SZ;
#pragma unroll
        for (int ks = 0; ks < 4; ks++) {
            uint32_t a[4][4], bfr[8][2];
#pragma unroll
            for (int i = 0; i < 4; i++) {
                const float* ap = As + (mw + i*16 + g)*AS_STR + ks*8 + t;
                a[i][0] = f2t(ap[0]);
                a[i][1] = f2t(ap[8*AS_STR]);
                a[i][2] = f2t(ap[4]);
                a[i][3] = f2t(ap[8*AS_STR + 4]);
            }
#pragma unroll
            for (int j = 0; j < 8; j++) {
                const float* bp = Ws + (ks*8 + t)*WS_STR + nw + j*8 + g;
                bfr[j][0] = f2t(bp[0]);
                bfr[j][1] = f2t(bp[4*WS_STR]);
            }
#pragma unroll
            for (int i = 0; i < 4; i++)
#pragma unroll
                for (int j = 0; j < 8; j++)
                    mma8(acc[i][j], a[i], bfr[j]);
        }
        __syncthreads();
    }

    // epilogue: + bias, round to tf32, store bits
#pragma unroll
    for (int j = 0; j < 8; j++) {
        int col = col0 + nw + j*8 + 2*t;
        float b0 = bias[col], b1 = bias[col + 1];
#pragma unroll
        for (int i = 0; i < 4; i++) {
            int row = row0 + mw + i*16 + g;
            uint2 v0 = make_uint2(f2t(acc[i][j][0] + b0), f2t(acc[i][j][1] + b1));
            uint2 v1 = make_uint2(f2t(acc[i][j][2] + b0), f2t(acc[i][j][3] + b1));
            *(uint2*)(Og + (long)row*HIDD + col) = v0;
            *(uint2*)(Og + (long)(row + 8)*HIDD + col) = v1;
        }
    }
}

// ---------------------------------------------------------------------------
// Pass 2: causal attention, tf32 mma.sync, no online max (bounded scores;
// masked weights ~e^-115 of row sum -> dropped exactly).
// Block: 256 threads (8 warps x 16 q-rows), q-tile 128, k-tile 64,
// double-buffered cp.async K/V pipeline.
// ---------------------------------------------------------------------------
#define KV_STR 132
#define PS_STR 68
#define KVTILE (64*KV_STR)                       // words per K or V tile
#define ASTAGE (2*KVTILE)                        // K+V per stage
#define PS_OFF (2*ASTAGE)                        // after two stages
#define ASM_BYTES ((2*ASTAGE + 128*PS_STR)*4)    // 169,984 B

__global__ __launch_bounds__(256)
void attn_kernel(float* __restrict__ out)
{
    extern __shared__ uint32_t sm[];
    uint32_t* Ps = sm + PS_OFF;

    const int tid = threadIdx.x;
    const int w = tid >> 5, lane = tid & 31;
    const int g = lane >> 2, t = lane & 3;
    const int m0 = w * 16;
    const int qt = 7 - blockIdx.x;            // biggest blocks first
    const int q0 = qt * 128;
    const int bh = blockIdx.y, b = bh >> 3, h = bh & 7;
    const int nk = 2*qt + 2;

    const uint32_t* Qg = g_Q + (long)b*SS*HIDD + h*DHH;
    const uint32_t* Kg = g_K + (long)b*SS*HIDD + h*DHH;
    const uint32_t* Vg = g_V + (long)b*SS*HIDD + h*DHH;

    // stage Q tile [128 x 128] through the (not yet used) stage buffers
    {
        uint32_t base = smaddr(sm);
#pragma unroll
        for (int c = 0; c < 16; c++) {
            int slot = tid + c*256;            // 0..4095
            int r = slot >> 5, cc = (slot & 31) * 4;
            CP16(base + (r*KV_STR + cc)*4, Qg + (long)(q0 + r)*HIDD + cc);
        }
        CPCOMMIT(); CPWAIT(0);
    }
    __syncthreads();

    uint32_t aQ[16][4];
#pragma unroll
    for (int ks = 0; ks < 16; ks++) {
        const uint32_t* qp = sm + (m0 + g)*KV_STR + ks*8 + t;
        aQ[ks][0] = qp[0];
        aQ[ks][1] = qp[8*KV_STR];
        aQ[ks][2] = qp[4];
        aQ[ks][3] = qp[8*KV_STR + 4];
    }
    __syncthreads();

    float accO[16][4];
#pragma unroll
    for (int j = 0; j < 16; j++)
#pragma unroll
        for (int e = 0; e < 4; e++) accO[j][e] = 0.0f;
    float l0 = 0.0f, l1 = 0.0f;
    const float scl = 0.08838834764831843f;   // 1/sqrt(128)

    auto issue = [&](int kt) {
        uint32_t base = smaddr(sm + (kt & 1)*ASTAGE);
        int k0 = kt * 64;
#pragma unroll
        for (int c = 0; c < 8; c++) {
            int slot = tid + c*256;            // 0..2047
            int r = slot >> 5, cc = (slot & 31) * 4;
            CP16(base + (r*KV_STR + cc)*4, Kg + (long)(k0 + r)*HIDD + cc);
            CP16(base + (KVTILE + r*KV_STR + cc)*4, Vg + (long)(k0 + r)*HIDD + cc);
        }
    };

    issue(0); CPCOMMIT();
    for (int kt = 0; kt < nk; kt++) {
        if (kt + 1 < nk) issue(kt + 1);
        CPCOMMIT();
        CPWAIT(1);
        __syncthreads();
        const uint32_t* Ks = sm + (kt & 1)*ASTAGE;
        const uint32_t* Vs = Ks + KVTILE;
        const int k0 = kt * 64;

        // S = Q K^T  (per warp: m16 x n64)
        float s[8][4];
#pragma unroll
        for (int j = 0; j < 8; j++)
#pragma unroll
            for (int e = 0; e < 4; e++) s[j][e] = 0.0f;
#pragma unroll
        for (int ks = 0; ks < 16; ks++) {
#pragma unroll
            for (int j = 0; j < 8; j++) {
                uint32_t bfr[2];
                const uint32_t* kp = Ks + (j*8 + g)*KV_STR + ks*8 + t;
                bfr[0] = kp[0];
                bfr[1] = kp[4];
                mma8(s[j], aQ[ks], bfr);
            }
        }

        // p = exp(exp(s/sqrt(d))), causal mask on near-diagonal tiles
        const int row_g  = q0 + m0 + g;
        const int row_g8 = row_g + 8;
        const bool diag = (k0 + 63 > row_g);   // any col could exceed a row
#pragma unroll
        for (int j = 0; j < 8; j++) {
            int c0 = k0 + j*8 + 2*t;
            float y0 = __expf(s[j][0]*scl), y1 = __expf(s[j][1]*scl);
            float y2 = __expf(s[j][2]*scl), y3 = __expf(s[j][3]*scl);
            float p0 = __expf(y0), p1 = __expf(y1);
            float p2 = __expf(y2), p3 = __expf(y3);
            if (diag) {
                if (c0     > row_g ) p0 = 0.0f;
                if (c0 + 1 > row_g ) p1 = 0.0f;
                if (c0     > row_g8) p2 = 0.0f;
                if (c0 + 1 > row_g8) p3 = 0.0f;
            }
            uint32_t u0 = f2t(p0), u1 = f2t(p1), u2 = f2t(p2), u3 = f2t(p3);
            l0 += __uint_as_float(u0) + __uint_as_float(u1);
            l1 += __uint_as_float(u2) + __uint_as_float(u3);
            *(uint2*)(Ps + (m0 + g)*PS_STR + j*8 + 2*t)     = make_uint2(u0, u1);
            *(uint2*)(Ps + (m0 + g + 8)*PS_STR + j*8 + 2*t) = make_uint2(u2, u3);
        }
        __syncwarp();

        // O += P V  (per warp: m16 x n128; P rows are warp-private)
#pragma unroll
        for (int ks = 0; ks < 8; ks++) {
            uint32_t aP[4];
            const uint32_t* pp = Ps + (m0 + g)*PS_STR + ks*8 + t;
            aP[0] = pp[0];
            aP[1] = pp[8*PS_STR];
            aP[2] = pp[4];
            aP[3] = pp[8*PS_STR + 4];
#pragma unroll
            for (int j = 0; j < 16; j++) {
                uint32_t bfr[2];
                const uint32_t* vp = Vs + (ks*8 + t)*KV_STR + j*8 + g;
                bfr[0] = vp[0];
                bfr[1] = vp[4*KV_STR];
                mma8(accO[j], aP, bfr);
            }
        }
        __syncthreads();
    }

    // row-sum reduce across the quad, normalize, store
    l0 += __shfl_xor_sync(0xffffffffu, l0, 1);
    l0 += __shfl_xor_sync(0xffffffffu, l0, 2);
    l1 += __shfl_xor_sync(0xffffffffu, l1, 1);
    l1 += __shfl_xor_sync(0xffffffffu, l1, 2);
    const float r0 = 1.0f / l0, r1 = 1.0f / l1;

    float* outp = out + ((long)b*SS + q0 + m0 + g)*HIDD + h*DHH;
#pragma unroll
    for (int j = 0; j < 16; j++) {
        int col = j*8 + 2*t;
        *(float2*)(outp + col)          = make_float2(accO[j][0]*r0, accO[j][1]*r0);
        *(float2*)(outp + 8*HIDD + col) = make_float2(accO[j][2]*r1, accO[j][3]*r1);
    }
}

// ---------------------------------------------------------------------------
extern "C" void kernel_launch(void* const* d_in, const int* in_sizes, int n_in,
                              void* d_out, int out_size)
{
    const float* queries = (const float*)d_in[0];
    const float* Wq = (const float*)d_in[1];
    const float* bq = (const float*)d_in[2];
    const float* Wk = (const float*)d_in[3];
    const float* bk = (const float*)d_in[4];
    const float* Wv = (const float*)d_in[5];
    const float* bv = (const float*)d_in[6];
    float* out = (float*)d_out;

    cudaFuncSetAttribute(qkv_mma_kernel, cudaFuncAttributeMaxDynamicSharedMemorySize, GSM_BYTES);
    cudaFuncSetAttribute(attn_kernel, cudaFuncAttributeMaxDynamicSharedMemorySize, ASM_BYTES);

    qkv_mma_kernel<<<dim3(8, 64, 3), 128, GSM_BYTES>>>(queries, Wq, bq, Wk, bk, Wv, bv);
    attn_kernel<<<dim3(8, 64), 256, ASM_BYTES>>>(out);
}